// round 1
// baseline (speedup 1.0000x reference)
#include <cuda_runtime.h>
#include <cstdint>

// Problem constants
#define BATCH 2048
#define TT    100
#define UD    512
#define G4    2048      // 4*UD
#define NCLS  10

// Tile constants
#define BM 128
#define BK 16
// block output tile: BM x (4 gates x 32 u) = 128 x 128

// smem layout (double-buffered A/B tiles; z-buffer unions on top)
#define OFF_A0 0
#define OFF_A1 10240           // A tile: 128 rows * 20 floats * 4B = 10240
#define OFF_B0 20480
#define OFF_B1 29184           // B tile: 16 rows * 136 floats * 4B = 8704
#define SMEM_BYTES 37888       // z-buffer (64*130*4 = 33280) fits inside

// ---------------- scratch (device globals; no allocation) ----------------
__device__ float g_h[3][2][BATCH * UD];   // [layer][t&1][b*UD+u]  24 MB
__device__ float g_c[3][BATCH * UD];      // 12 MB
__device__ float g_Ut[3][UD * G4];        // tf32-rounded U matrices, 12 MB
__device__ float g_Wt[2][UD * G4];        // tf32-rounded W for layers 1,2, 8 MB
__device__ int   g_mask4;                 // 1 if mask elements are 4 bytes

__device__ __forceinline__ float to_tf32(float v) {
    uint32_t r;
    asm("cvt.rna.tf32.f32 %0, %1;" : "=r"(r) : "f"(v));
    return __uint_as_float(r);
}

__device__ __forceinline__ float sigf(float x) {
    return 1.0f / (1.0f + expf(-x));
}

#define CP16(dst, src) \
    asm volatile("cp.async.cg.shared.global [%0], [%1], 16;\n" :: "r"(dst), "l"(src))

#define MMA_TF32(d, a, b) \
    asm volatile("mma.sync.aligned.m16n8k8.row.col.f32.tf32.tf32.f32 " \
        "{%0,%1,%2,%3},{%4,%5,%6,%7},{%8,%9},{%0,%1,%2,%3};\n" \
        : "+f"(d[0]), "+f"(d[1]), "+f"(d[2]), "+f"(d[3]) \
        : "r"(a[0]), "r"(a[1]), "r"(a[2]), "r"(a[3]), "r"(b[0]), "r"(b[1]))

// ---------------- mask dtype detection ----------------
// bytes at offset 1 (mod 4): int8 bool -> ~50% nonzero; int32/float32 -> all zero.
__global__ void k_detect(const unsigned char* __restrict__ mask) {
    __shared__ int found;
    if (threadIdx.x == 0) found = 0;
    __syncthreads();
    for (int i = threadIdx.x * 4 + 1; i < 4096; i += blockDim.x * 4)
        if (mask[i]) found = 1;
    __syncthreads();
    if (threadIdx.x == 0) g_mask4 = found ? 0 : 1;
}

// ---------------- zero states ----------------
__global__ void k_zero() {
    const float4 z4 = make_float4(0.f, 0.f, 0.f, 0.f);
    size_t nh = (size_t)3 * 2 * BATCH * UD / 4;
    float4* ph = (float4*)&g_h[0][0][0];
    for (size_t i = (size_t)blockIdx.x * blockDim.x + threadIdx.x; i < nh;
         i += (size_t)gridDim.x * blockDim.x)
        ph[i] = z4;
    size_t nc = (size_t)3 * BATCH * UD / 4;
    float4* pc = (float4*)&g_c[0][0];
    for (size_t i = (size_t)blockIdx.x * blockDim.x + threadIdx.x; i < nc;
         i += (size_t)gridDim.x * blockDim.x)
        pc[i] = z4;
}

// ---------------- round weights to tf32 once per launch ----------------
__global__ void k_round(const float* __restrict__ U0, const float* __restrict__ U1,
                        const float* __restrict__ U2, const float* __restrict__ W1,
                        const float* __restrict__ W2) {
    const int N1 = UD * G4;  // 1048576
    size_t total = (size_t)5 * N1;
    for (size_t i = (size_t)blockIdx.x * blockDim.x + threadIdx.x; i < total;
         i += (size_t)gridDim.x * blockDim.x) {
        int j = (int)(i >> 20);
        int lo = (int)(i & (N1 - 1));
        const float* src;
        float* dst;
        switch (j) {
            case 0: src = U0; dst = g_Ut[0]; break;
            case 1: src = U1; dst = g_Ut[1]; break;
            case 2: src = U2; dst = g_Ut[2]; break;
            case 3: src = W1; dst = g_Wt[0]; break;
            default: src = W2; dst = g_Wt[1]; break;
        }
        dst[lo] = to_tf32(src[lo]);
    }
}

// ---------------- fused LSTM step (3 layers wavefront-pipelined) ----------------
__global__ __launch_bounds__(256, 2) void lstm_step(
    const float* __restrict__ x,      // (B, T)
    const void* __restrict__ mask,    // (B, T), 1B or 4B elements
    const float* __restrict__ W0row,  // (2048) layer-0 input weights (in_dim=1)
    const float* __restrict__ b0,
    const float* __restrict__ b1,
    const float* __restrict__ b2,
    int s)
{
    const int layer = blockIdx.z;
    const int t = s - layer;
    if (t < 0 || t >= TT) return;

    const int m0 = blockIdx.x * BM;
    const int u0 = blockIdx.y * 32;
    const int tid = threadIdx.x;

    const float* hprev = g_h[layer][(t + 1) & 1];
    float*       hout  = g_h[layer][t & 1];
    float*       cbuf  = g_c[layer];
    const float* in0   = (layer == 0) ? nullptr : g_h[layer - 1][t & 1];
    const float* Wsrc  = (layer == 0) ? nullptr : g_Wt[layer - 1];
    const float* Usrc  = g_Ut[layer];
    const float* bias  = (layer == 0) ? b0 : ((layer == 1) ? b1 : b2);

    __shared__ __align__(16) char smembuf[SMEM_BYTES];

    const int KT = (layer == 0) ? 32 : 64;

    // --- cp.async tile issue ---
    auto issue = [&](int kt) {
        const float* As; const float* Bs; int kk;
        if (layer > 0 && kt < 32) { As = in0;  Bs = Wsrc; kk = kt << 4; }
        else                      { As = hprev; Bs = Usrc; kk = (kt - ((layer > 0) ? 32 : 0)) << 4; }
        const int buf = kt & 1;
        uint32_t aB = (uint32_t)__cvta_generic_to_shared(smembuf + (buf ? OFF_A1 : OFF_A0));
        uint32_t bB = (uint32_t)__cvta_generic_to_shared(smembuf + (buf ? OFF_B1 : OFF_B0));
        #pragma unroll
        for (int it = 0; it < 2; it++) {
            int i = tid + it * 256;
            int m = i >> 2, k4 = i & 3;
            const float* src = As + (size_t)(m0 + m) * UD + kk + k4 * 4;
            CP16(aB + (uint32_t)(m * 20 + k4 * 4) * 4, src);
        }
        #pragma unroll
        for (int it = 0; it < 2; it++) {
            int i = tid + it * 256;
            int k = i >> 5, r = i & 31;
            int band = r >> 3, q = r & 7;
            const float* src = Bs + (size_t)(kk + k) * G4 + band * UD + u0 + q * 4;
            CP16(bB + (uint32_t)(k * 136 + band * 32 + q * 4) * 4, src);
        }
        asm volatile("cp.async.commit_group;\n" ::);
    };

    // --- warp / fragment decomposition ---
    const int lane = tid & 31, wid = tid >> 5;
    const int g  = lane >> 2, tg = lane & 3;
    const int wm = wid & 1, wn = wid >> 1;
    const int moff = wm * 64, noff = wn * 32;

    float acc[4][4][4];
    #pragma unroll
    for (int i = 0; i < 4; i++)
        #pragma unroll
        for (int j = 0; j < 4; j++)
            #pragma unroll
            for (int q = 0; q < 4; q++) acc[i][j][q] = 0.f;

    issue(0);

    for (int kt = 0; kt < KT; kt++) {
        if (kt + 1 < KT) {
            issue(kt + 1);
            asm volatile("cp.async.wait_group 1;\n" ::);
        } else {
            asm volatile("cp.async.wait_group 0;\n" ::);
        }
        __syncthreads();

        const uint32_t* Ab = (const uint32_t*)(smembuf + ((kt & 1) ? OFF_A1 : OFF_A0));
        const uint32_t* Bb = (const uint32_t*)(smembuf + ((kt & 1) ? OFF_B1 : OFF_B0));

        #pragma unroll
        for (int ks = 0; ks < 2; ks++) {
            uint32_t a[4][4], b[4][2];
            #pragma unroll
            for (int mt = 0; mt < 4; mt++) {
                int r0 = moff + mt * 16 + g;
                a[mt][0] = Ab[r0 * 20 + ks * 8 + tg];
                a[mt][1] = Ab[(r0 + 8) * 20 + ks * 8 + tg];
                a[mt][2] = Ab[r0 * 20 + ks * 8 + tg + 4];
                a[mt][3] = Ab[(r0 + 8) * 20 + ks * 8 + tg + 4];
            }
            #pragma unroll
            for (int nt = 0; nt < 4; nt++) {
                b[nt][0] = Bb[(ks * 8 + tg) * 136 + noff + nt * 8 + g];
                b[nt][1] = Bb[(ks * 8 + tg + 4) * 136 + noff + nt * 8 + g];
            }
            #pragma unroll
            for (int mt = 0; mt < 4; mt++)
                #pragma unroll
                for (int nt = 0; nt < 4; nt++)
                    MMA_TF32(acc[mt][nt], a[mt], b[nt]);
        }
        __syncthreads();
    }

    // --- fused epilogue: z -> gates -> (h, c), mask applied ---
    const int mask4 = g_mask4;
    const int uu = tid & 31;
    const int u  = u0 + uu;
    const float bi = bias[u], bf = bias[UD + u], bg = bias[2 * UD + u], bo = bias[3 * UD + u];
    float w0i = 0.f, w0f = 0.f, w0g = 0.f, w0o = 0.f;
    if (layer == 0) {
        w0i = W0row[u]; w0f = W0row[UD + u];
        w0g = W0row[2 * UD + u]; w0o = W0row[3 * UD + u];
    }
    float* zsm = (float*)smembuf;   // 64 x 130

    for (int half = 0; half < 2; half++) {
        __syncthreads();
        if (wm == half) {
            #pragma unroll
            for (int mt = 0; mt < 4; mt++) {
                #pragma unroll
                for (int nt = 0; nt < 4; nt++) {
                    int rl = mt * 16 + g;
                    int cb = noff + nt * 8 + 2 * tg;
                    zsm[rl * 130 + cb]       = acc[mt][nt][0];
                    zsm[rl * 130 + cb + 1]   = acc[mt][nt][1];
                    zsm[(rl + 8) * 130 + cb]     = acc[mt][nt][2];
                    zsm[(rl + 8) * 130 + cb + 1] = acc[mt][nt][3];
                }
            }
        }
        __syncthreads();

        #pragma unroll
        for (int r = 0; r < 8; r++) {
            int ml = (tid >> 5) + r * 8;
            int brow = m0 + half * 64 + ml;
            float zi = zsm[ml * 130 + uu]      + bi;
            float zf = zsm[ml * 130 + 32 + uu] + bf;
            float zg = zsm[ml * 130 + 64 + uu] + bg;
            float zo = zsm[ml * 130 + 96 + uu] + bo;
            if (layer == 0) {
                float xv = x[(size_t)brow * TT + t];
                zi += xv * w0i; zf += xv * w0f; zg += xv * w0g; zo += xv * w0o;
            }
            float ii = sigf(zi);
            float ff = sigf(zf);
            float gg = tanhf(zg);
            float oo = sigf(zo);

            size_t idx = (size_t)brow * UD + u;
            float co = cbuf[idx];
            float cn = ff * co + ii * gg;
            float hn = oo * tanhf(cn);

            size_t midx = (size_t)brow * TT + t;
            bool msk = mask4 ? (((const unsigned int*)mask)[midx] != 0u)
                             : (((const unsigned char*)mask)[midx] != 0);
            if (msk) {
                cbuf[idx] = cn;
                hout[idx] = to_tf32(hn);
            } else {
                hout[idx] = hprev[idx];
            }
        }
    }
}

// ---------------- head: logits + softmax ----------------
__global__ void k_head(const float* __restrict__ Wd, const float* __restrict__ bd,
                       float* __restrict__ out) {
    __shared__ float wds[UD * NCLS];
    __shared__ float bds[NCLS];
    int tid = threadIdx.x;
    for (int i = tid; i < UD * NCLS; i += 256) wds[i] = Wd[i];
    if (tid < NCLS) bds[tid] = bd[tid];
    __syncthreads();

    int wid = tid >> 5, lane = tid & 31;
    int b = blockIdx.x * 8 + wid;
    const float* h = g_h[2][(TT - 1) & 1];

    float p[NCLS];
    #pragma unroll
    for (int c = 0; c < NCLS; c++) p[c] = 0.f;
    for (int k = lane; k < UD; k += 32) {
        float hv = h[(size_t)b * UD + k];
        #pragma unroll
        for (int c = 0; c < NCLS; c++) p[c] += hv * wds[k * NCLS + c];
    }
    #pragma unroll
    for (int off = 16; off; off >>= 1)
        #pragma unroll
        for (int c = 0; c < NCLS; c++)
            p[c] += __shfl_down_sync(0xffffffffu, p[c], off);

    if (lane == 0) {
        float l[NCLS], mx = -1e30f;
        #pragma unroll
        for (int c = 0; c < NCLS; c++) { l[c] = p[c] + bds[c]; mx = fmaxf(mx, l[c]); }
        float ssum = 0.f;
        #pragma unroll
        for (int c = 0; c < NCLS; c++) { l[c] = expf(l[c] - mx); ssum += l[c]; }
        float inv = 1.0f / ssum;
        #pragma unroll
        for (int c = 0; c < NCLS; c++) out[(size_t)b * NCLS + c] = l[c] * inv;
    }
}

// ---------------- launch ----------------
extern "C" void kernel_launch(void* const* d_in, const int* in_sizes, int n_in,
                              void* d_out, int out_size) {
    const float* x    = (const float*)d_in[0];
    const void*  mask = d_in[1];
    const float* W0   = (const float*)d_in[2];
    const float* U0   = (const float*)d_in[3];
    const float* b0   = (const float*)d_in[4];
    const float* W1   = (const float*)d_in[5];
    const float* U1   = (const float*)d_in[6];
    const float* b1   = (const float*)d_in[7];
    const float* W2   = (const float*)d_in[8];
    const float* U2   = (const float*)d_in[9];
    const float* b2   = (const float*)d_in[10];
    const float* Wd   = (const float*)d_in[11];
    const float* bd   = (const float*)d_in[12];
    float* out = (float*)d_out;

    k_detect<<<1, 256>>>((const unsigned char*)mask);
    k_zero<<<2048, 256>>>();
    k_round<<<2560, 256>>>(U0, U1, U2, W1, W2);

    dim3 grid(BATCH / BM, UD / 32, 3);
    for (int s = 0; s < TT + 2; s++) {
        lstm_step<<<grid, 256>>>(x, mask, W0, b0, b1, b2, s);
    }
    k_head<<<BATCH / 8, 256>>>(Wd, bd, out);
}